// round 5
// baseline (speedup 1.0000x reference)
#include <cuda_runtime.h>
#include <cuda_fp16.h>

#define NB 64
#define NT 512
#define DIN 512
#define HID 1024
#define NCTA 128
#define NTHR 256

// ---------------- global scratch ----------------
__device__ __align__(256) __half g_Xh[NT*NB*DIN];
__device__ __align__(256) __half g_X1[NT*NB*HID];
__device__ __align__(256) float  g_GB[(size_t)NT*NB*4*HID];
__device__ __align__(256) __half g_W0T[4*HID*DIN];
__device__ __align__(256) __half g_W1T[4*HID*HID];
__device__ __align__(256) __half g_U0T[4*HID*HID];
__device__ __align__(256) __half g_U1T[4*HID*HID];
__device__ __align__(256) __half g_H[2][NB*HID];
__device__ unsigned g_bar;

// ---------------- helpers ----------------
__device__ __forceinline__ unsigned sptr(const void* p) {
  return (unsigned)__cvta_generic_to_shared(p);
}
__device__ __forceinline__ void cp16(unsigned d, const void* s) {
  asm volatile("cp.async.cg.shared.global [%0], [%1], 16;" :: "r"(d), "l"(s));
}
__device__ __forceinline__ void cpcommit() { asm volatile("cp.async.commit_group;"); }
__device__ __forceinline__ void cpwait0()  { asm volatile("cp.async.wait_group 0;"); }
__device__ __forceinline__ void cpwait1()  { asm volatile("cp.async.wait_group 1;"); }
__device__ __forceinline__ void cpwait2()  { asm volatile("cp.async.wait_group 2;"); }

__device__ __forceinline__ void ldsm4(unsigned* r, unsigned addr) {
  asm volatile("ldmatrix.sync.aligned.m8n8.x4.shared.b16 {%0,%1,%2,%3}, [%4];"
    : "=r"(r[0]), "=r"(r[1]), "=r"(r[2]), "=r"(r[3]) : "r"(addr));
}
__device__ __forceinline__ void hmma(float* d, const unsigned* a, const unsigned* b) {
  asm volatile("mma.sync.aligned.m16n8k16.row.col.f32.f16.f16.f32 "
    "{%0,%1,%2,%3}, {%4,%5,%6,%7}, {%8,%9}, {%0,%1,%2,%3};"
    : "+f"(d[0]), "+f"(d[1]), "+f"(d[2]), "+f"(d[3])
    : "r"(a[0]), "r"(a[1]), "r"(a[2]), "r"(a[3]), "r"(b[0]), "r"(b[1]));
}
__device__ __forceinline__ void gridbar() {
  __syncthreads();
  if (threadIdx.x == 0) {
    unsigned t, cur;
    asm volatile("atom.add.release.gpu.u32 %0, [%1], 1;" : "=r"(t) : "l"(&g_bar) : "memory");
    unsigned target = (t & ~(unsigned)(NCTA-1)) + NCTA;
    do {
      asm volatile("ld.acquire.gpu.u32 %0, [%1];" : "=r"(cur) : "l"(&g_bar) : "memory");
    } while ((int)(cur - target) < 0);
  }
  __syncthreads();
}
__device__ __forceinline__ float sigf(float x)     { return 1.f/(1.f+__expf(-x)); }
__device__ __forceinline__ float tanhfast(float x) { return 1.f - 2.f/(1.f+__expf(2.f*x)); }

// ---------------- prep kernels ----------------
extern "C" __global__ void conv_x_kernel(const float* x) {
  for (size_t idx = (size_t)blockIdx.x*blockDim.x + threadIdx.x;
       idx < (size_t)NB*NT*DIN; idx += (size_t)gridDim.x*blockDim.x) {
    int d = (int)(idx & (DIN-1));
    int t = (int)((idx >> 9) & (NT-1));
    int b = (int)(idx >> 18);
    g_Xh[((size_t)(t*NB + b))*DIN + d] = __float2half_rn(x[idx]);
  }
}

extern "C" __global__ void transpose_kernel(const float* in, __half* out, int R, int C) {
  __shared__ float tile[32][33];
  int cx = blockIdx.x*32, ry = blockIdx.y*32;
  #pragma unroll
  for (int j = 0; j < 4; ++j) {
    int r = ry + threadIdx.y + j*8;
    tile[threadIdx.y + j*8][threadIdx.x] = in[(size_t)r*C + cx + threadIdx.x];
  }
  __syncthreads();
  #pragma unroll
  for (int j = 0; j < 4; ++j) {
    int ro = cx + threadIdx.y + j*8;
    out[(size_t)ro*R + ry + threadIdx.x] = __float2half_rn(tile[threadIdx.x][threadIdx.y + j*8]);
  }
}

// ---------------- prepass GEMM: C[M,4096] = A[M,K] @ WT^T + bias ----------------
// Tile 128m x 128n, 8 warps = 2m x 4n (warp tile 64x32), k-chunk 64, 3-stage.
#define GA_PITCH 144              // bytes per staged row (64 halves + pad)
#define GST (128*GA_PITCH)        // 18432 per operand per stage
#define GSTB (2*GST)              // 36864 per stage
#define GNST 3
#define GSMEM (GNST*GSTB)         // 110592

extern "C" __global__ void __launch_bounds__(NTHR, 2)
gemm_kernel(const __half* A, const __half* WT, const float* bias, float* C, int K) {
  extern __shared__ char sm[];
  const int tid = threadIdx.x, lane = tid&31, wid = tid>>5;
  const int wm = wid>>2, wn = wid&3;        // 2m x 4n warps
  const int r = lane>>2, c2 = lane&3;
  const int sub = lane>>3, rsel = lane&7;
  const int bm = blockIdx.x, bn = blockIdx.y;
  const int NC = K >> 6;
  const unsigned sbase = sptr(sm);

  float acc[4][4][4];   // [m16 tile][n8 tile][frag]
  #pragma unroll
  for (int j = 0; j < 4; ++j) {
    float2 bv = *(const float2*)(bias + bn*128 + wn*32 + j*8 + 2*c2);
    #pragma unroll
    for (int mt = 0; mt < 4; ++mt) {
      acc[mt][j][0]=bv.x; acc[mt][j][1]=bv.y; acc[mt][j][2]=bv.x; acc[mt][j][3]=bv.y;
    }
  }

#define GSTG(CH) do {                                                       \
    unsigned base = sbase + ((CH)%3)*GSTB;                                  \
    _Pragma("unroll")                                                       \
    for (int jj = 0; jj < 4; ++jj) {                                        \
      int idx = tid + jj*NTHR, row = idx>>3, seg = idx&7;                   \
      cp16(base + row*GA_PITCH + seg*16,                                    \
           A + (size_t)(bm*128+row)*K + (CH)*64 + seg*8);                   \
      cp16(base + GST + row*GA_PITCH + seg*16,                              \
           WT + (size_t)(bn*128+row)*K + (CH)*64 + seg*8);                  \
    }                                                                       \
    cpcommit();                                                             \
  } while(0)

  GSTG(0); GSTG(1);
  #pragma unroll 1
  for (int ch = 0; ch < NC; ++ch) {
    if (ch+2 < NC) { GSTG(ch+2); cpwait2(); }
    else if (ch+1 < NC) cpwait1();
    else cpwait0();
    __syncthreads();
    unsigned ab = sbase + (ch%3)*GSTB;
    unsigned bb = ab + GST;
    #pragma unroll
    for (int s = 0; s < 4; ++s) {
      unsigned av[4][4];
      #pragma unroll
      for (int mt = 0; mt < 4; ++mt)
        ldsm4(av[mt], ab + (wm*64 + mt*16 + (sub&1)*8 + rsel)*GA_PITCH
                         + s*32 + (sub>>1)*16);
      #pragma unroll
      for (int nt = 0; nt < 2; ++nt) {
        unsigned bv[4];
        ldsm4(bv, bb + (wn*32 + nt*16 + (sub>>1)*8 + rsel)*GA_PITCH
                     + s*32 + (sub&1)*16);
        #pragma unroll
        for (int mt = 0; mt < 4; ++mt) {
          hmma(acc[mt][nt*2],   av[mt], bv);
          hmma(acc[mt][nt*2+1], av[mt], bv+2);
        }
      }
    }
    __syncthreads();
  }
#undef GSTG

  #pragma unroll
  for (int mt = 0; mt < 4; ++mt) {
    int row = bm*128 + wm*64 + mt*16 + r;
    #pragma unroll
    for (int j = 0; j < 4; ++j) {
      int col = bn*128 + wn*32 + j*8 + 2*c2;
      float* p = C + (size_t)row*4096 + col;
      *(float2*)p            = make_float2(acc[mt][j][0], acc[mt][j][1]);
      *(float2*)(p + 8*4096) = make_float2(acc[mt][j][2], acc[mt][j][3]);
    }
  }
}

// ---------------- recurrent kernel ----------------
#define AWP 528                 // bytes per staged A row (264 halves)
#define AWB (32*AWP)            // 16896 per warp
#define UPH 1032                // U bounce pitch (halves)
#define RPACC_OFF 135168
#define RPACC_PITCH 40
#define RGB_OFF  176128         // 64 x 40 floats = 10240
#define RGB_PITCH 40
#define RCS_OFF  186368
#define RSMEM    188416

template<int LAYER>
__global__ void __launch_bounds__(NTHR, 1)
rec_kernel(const float* h0, const float* c0, const __half* UT,
           float* out, int out_size)
{
  extern __shared__ char sm[];
  float* pacc = (float*)(sm + RPACC_OFF);
  float* gbs  = (float*)(sm + RGB_OFF);
  float* cs   = (float*)(sm + RCS_OFF);
  const int tid = threadIdx.x, cta = blockIdx.x;
  const int lane = tid&31, wid = tid>>5;
  const int wm = wid&1, ks = wid>>1;
  const int r = lane>>2, c2 = lane&3;
  const int sub = lane>>3, rsel = lane&7;

  // ---- init c, h0 ----
  #pragma unroll
  for (int e0 = 0; e0 < 2; ++e0) {
    int item = tid + e0*NTHR;
    int b = item>>3, hc = item&7, col = cta*8 + hc;
    cs[item] = c0[b*HID + col];
    g_H[0][b*HID + col] = __float2half_rn(h0[b*HID + col]);
  }

  // ---- U bounce -> register fragments ----
  {
    __half* ub = (__half*)sm;
    unsigned du = sptr(ub);
    #pragma unroll
    for (int j = 0; j < 16; ++j) {
      int idx = tid + j*NTHR;
      int row = idx >> 7, seg = idx & 127;
      int gcol = (row>>3)*HID + cta*8 + (row&7);
      cp16(du + row*(UPH*2) + seg*16, UT + (size_t)gcol*HID + seg*8);
    }
    cpcommit(); cpwait0();
  }
  __syncthreads();

  unsigned bfr[16][4][2];
  {
    const __half* ub = (const __half*)sm;
    #pragma unroll
    for (int s = 0; s < 16; ++s) {
      int k = ks*256 + s*16 + 2*c2;
      #pragma unroll
      for (int nt = 0; nt < 4; ++nt) {
        const __half* p = ub + (nt*8 + r)*UPH + k;
        bfr[s][nt][0] = *(const unsigned*)(p);
        bfr[s][nt][1] = *(const unsigned*)(p + 8);
      }
    }
  }
  __syncthreads();
  gridbar();

  unsigned wbs = sptr(sm) + wid*AWB;
  unsigned gbd = sptr(sm + RGB_OFF);

  for (int t = 0; t < NT; ++t) {
    const __half* hs = g_H[t&1];

    // group 0: gate-base prefetch (8KB for this step)
    #pragma unroll
    for (int j = 0; j < 2; ++j) {
      int idx = tid + j*NTHR;
      int b = idx>>3, q = idx&7;            // gate=q>>1, half=q&1
      cp16(gbd + (b*RGB_PITCH + (q>>1)*8 + (q&1)*4)*4,
           g_GB + ((size_t)(t*NB + b))*4096 + (q>>1)*1024 + cta*8 + (q&1)*4);
    }
    cpcommit();

    // group 1: A k-half 0 ; group 2: A k-half 1 (warp-private 32 rows x 256 halves)
    {
      int rofs = lane>>4, seg = lane&15;
      #pragma unroll
      for (int i = 0; i < 16; ++i) {
        int row = 2*i + rofs;
        cp16(wbs + row*AWP + seg*16,
             hs + (size_t)(wm*32 + row)*HID + ks*256 + seg*8);
      }
      cpcommit();
      #pragma unroll
      for (int i = 0; i < 16; ++i) {
        int row = 2*i + rofs;
        cp16(wbs + row*AWP + 256 + seg*16,
             hs + (size_t)(wm*32 + row)*HID + ks*256 + 128 + seg*8);
      }
      cpcommit();
    }

    float acc[2][4][4];
    #pragma unroll
    for (int mt = 0; mt < 2; ++mt)
      #pragma unroll
      for (int nt = 0; nt < 4; ++nt)
        acc[mt][nt][0]=acc[mt][nt][1]=acc[mt][nt][2]=acc[mt][nt][3]=0.f;

    cpwait1(); __syncwarp();
    #pragma unroll
    for (int s = 0; s < 8; ++s) {
      unsigned av[2][4];
      #pragma unroll
      for (int mt = 0; mt < 2; ++mt)
        ldsm4(av[mt], wbs + (mt*16 + (sub&1)*8 + rsel)*AWP + s*32 + (sub>>1)*16);
      #pragma unroll
      for (int nt = 0; nt < 4; ++nt)
        #pragma unroll
        for (int mt = 0; mt < 2; ++mt)
          hmma(acc[mt][nt], av[mt], bfr[s][nt]);
    }
    cpwait0(); __syncwarp();
    #pragma unroll
    for (int s = 8; s < 16; ++s) {
      unsigned av[2][4];
      #pragma unroll
      for (int mt = 0; mt < 2; ++mt)
        ldsm4(av[mt], wbs + (mt*16 + (sub&1)*8 + rsel)*AWP + s*32 + (sub>>1)*16);
      #pragma unroll
      for (int nt = 0; nt < 4; ++nt)
        #pragma unroll
        for (int mt = 0; mt < 2; ++mt)
          hmma(acc[mt][nt], av[mt], bfr[s][nt]);
    }

    // k-split partials
    #pragma unroll
    for (int mt = 0; mt < 2; ++mt) {
      int row = wm*32 + mt*16 + r;
      #pragma unroll
      for (int nt = 0; nt < 4; ++nt) {
        int col = nt*8 + 2*c2;
        float* p = pacc + (ks*64 + row)*RPACC_PITCH + col;
        *(float2*)p                   = make_float2(acc[mt][nt][0], acc[mt][nt][1]);
        *(float2*)(p + 8*RPACC_PITCH) = make_float2(acc[mt][nt][2], acc[mt][nt][3]);
      }
    }
    __syncthreads();

    // reduce + gate base + cell update
    #pragma unroll
    for (int e0 = 0; e0 < 2; ++e0) {
      int item = tid + e0*NTHR;
      int b = item>>3, hc = item&7;
      const float* gb = gbs + b*RGB_PITCH;
      float gi=gb[hc], gf=gb[8+hc], gg=gb[16+hc], go=gb[24+hc];
      #pragma unroll
      for (int q = 0; q < 4; ++q) {
        const float* p = pacc + (q*64 + b)*RPACC_PITCH;
        gi += p[hc]; gf += p[8+hc]; gg += p[16+hc]; go += p[24+hc];
      }
      float cprev = cs[item];
      float cn = sigf(gf)*cprev + sigf(gi)*tanhfast(gg);
      float hn = sigf(go)*tanhfast(cn);
      cs[item] = cn;
      int col = cta*8 + hc;
      g_H[(t+1)&1][b*HID + col] = __float2half_rn(hn);
      if (LAYER == 0) {
        g_X1[((size_t)(t*NB + b))*HID + col] = __float2half_rn(hn);
      } else {
        out[((size_t)b*NT + t)*HID + col] = hn;
        if (t == NT-1 && out_size >= NB*NT*HID + 2*NB*HID) {
          out[(size_t)NB*NT*HID + b*HID + col]          = hn;
          out[(size_t)NB*NT*HID + NB*HID + b*HID + col] = cn;
        }
      }
    }
    gridbar();
  }
}

// ---------------- host launch ----------------
extern "C" void kernel_launch(void* const* d_in, const int* in_sizes, int n_in,
                              void* d_out, int out_size) {
  const float* x  = (const float*)d_in[0];
  const float* h0 = (const float*)d_in[1];
  const float* c0 = (const float*)d_in[2];
  const float* W0 = (const float*)d_in[3];
  const float* U0 = (const float*)d_in[4];
  const float* b0 = (const float*)d_in[5];
  const float* W1 = (const float*)d_in[6];
  const float* U1 = (const float*)d_in[7];
  const float* b1 = (const float*)d_in[8];
  float* out = (float*)d_out;

  cudaFuncSetAttribute(gemm_kernel, cudaFuncAttributeMaxDynamicSharedMemorySize, GSMEM);
  cudaFuncSetAttribute(rec_kernel<0>, cudaFuncAttributeMaxDynamicSharedMemorySize, RSMEM);
  cudaFuncSetAttribute(rec_kernel<1>, cudaFuncAttributeMaxDynamicSharedMemorySize, RSMEM);

  __half *pW0T, *pW1T, *pU0T, *pU1T, *pXh, *pX1;
  float* pGB;
  cudaGetSymbolAddress((void**)&pW0T, g_W0T);
  cudaGetSymbolAddress((void**)&pW1T, g_W1T);
  cudaGetSymbolAddress((void**)&pU0T, g_U0T);
  cudaGetSymbolAddress((void**)&pU1T, g_U1T);
  cudaGetSymbolAddress((void**)&pXh,  g_Xh);
  cudaGetSymbolAddress((void**)&pX1,  g_X1);
  cudaGetSymbolAddress((void**)&pGB,  g_GB);

  conv_x_kernel<<<512, 256>>>(x);
  dim3 tb(32, 8);
  transpose_kernel<<<dim3(4*HID/32, DIN/32), tb>>>(W0, pW0T, DIN, 4*HID);
  transpose_kernel<<<dim3(4*HID/32, HID/32), tb>>>(W1, pW1T, HID, 4*HID);
  transpose_kernel<<<dim3(4*HID/32, HID/32), tb>>>(U0, pU0T, HID, 4*HID);
  transpose_kernel<<<dim3(4*HID/32, HID/32), tb>>>(U1, pU1T, HID, 4*HID);

  gemm_kernel<<<dim3(NT*NB/128, 4*HID/128), NTHR, GSMEM>>>(pXh, pW0T, b0, pGB, DIN);
  rec_kernel<0><<<NCTA, NTHR, RSMEM>>>(h0, c0, pU0T, out, out_size);
  gemm_kernel<<<dim3(NT*NB/128, 4*HID/128), NTHR, GSMEM>>>(pX1, pW1T, b1, pGB, HID);
  rec_kernel<1><<<NCTA, NTHR, RSMEM>>>(h0 + NB*HID, c0 + NB*HID, pU1T, out, out_size);
}

// round 7
// speedup vs baseline: 1.3828x; 1.3828x over previous
#include <cuda_runtime.h>
#include <cuda_fp16.h>

#define NB 64
#define NT 512
#define DIN 512
#define HID 1024
#define NCTA 128
#define NTHR 256

// ---------------- global scratch ----------------
__device__ __align__(256) __half g_Xh[NT*NB*DIN];
__device__ __align__(256) __half g_X1[NT*NB*HID];
__device__ __align__(256) float  g_GB[(size_t)NT*NB*4*HID];
__device__ __align__(256) __half g_W0T[4*HID*DIN];
__device__ __align__(256) __half g_W1T[4*HID*HID];
__device__ __align__(256) __half g_U0T[4*HID*HID];
__device__ __align__(256) __half g_U1T[4*HID*HID];
__device__ __align__(256) __half g_H[2][NB*HID];
__device__ unsigned g_bar;

// ---------------- helpers ----------------
__device__ __forceinline__ unsigned sptr(const void* p) {
  return (unsigned)__cvta_generic_to_shared(p);
}
__device__ __forceinline__ void cp16(unsigned d, const void* s) {
  asm volatile("cp.async.cg.shared.global [%0], [%1], 16;" :: "r"(d), "l"(s));
}
__device__ __forceinline__ void cpcommit() { asm volatile("cp.async.commit_group;"); }
__device__ __forceinline__ void cpwait0()  { asm volatile("cp.async.wait_group 0;"); }
__device__ __forceinline__ void cpwait1()  { asm volatile("cp.async.wait_group 1;"); }
__device__ __forceinline__ void cpwait2()  { asm volatile("cp.async.wait_group 2;"); }

__device__ __forceinline__ void ldsm4(unsigned* r, unsigned addr) {
  asm volatile("ldmatrix.sync.aligned.m8n8.x4.shared.b16 {%0,%1,%2,%3}, [%4];"
    : "=r"(r[0]), "=r"(r[1]), "=r"(r[2]), "=r"(r[3]) : "r"(addr));
}
__device__ __forceinline__ void hmma(float* d, const unsigned* a, const unsigned* b) {
  asm volatile("mma.sync.aligned.m16n8k16.row.col.f32.f16.f16.f32 "
    "{%0,%1,%2,%3}, {%4,%5,%6,%7}, {%8,%9}, {%0,%1,%2,%3};"
    : "+f"(d[0]), "+f"(d[1]), "+f"(d[2]), "+f"(d[3])
    : "r"(a[0]), "r"(a[1]), "r"(a[2]), "r"(a[3]), "r"(b[0]), "r"(b[1]));
}
__device__ __forceinline__ void gridbar() {
  __syncthreads();
  if (threadIdx.x == 0) {
    unsigned t, cur;
    asm volatile("atom.add.release.gpu.u32 %0, [%1], 1;" : "=r"(t) : "l"(&g_bar) : "memory");
    unsigned target = (t & ~(unsigned)(NCTA-1)) + NCTA;
    do {
      asm volatile("ld.acquire.gpu.u32 %0, [%1];" : "=r"(cur) : "l"(&g_bar) : "memory");
    } while ((int)(cur - target) < 0);
  }
  __syncthreads();
}
__device__ __forceinline__ float sigf(float x)     { return 1.f/(1.f+__expf(-x)); }
__device__ __forceinline__ float tanhfast(float x) { return 1.f - 2.f/(1.f+__expf(2.f*x)); }

// ---------------- prep kernels ----------------
extern "C" __global__ void conv_x_kernel(const float* x) {
  for (size_t idx = (size_t)blockIdx.x*blockDim.x + threadIdx.x;
       idx < (size_t)NB*NT*DIN; idx += (size_t)gridDim.x*blockDim.x) {
    int d = (int)(idx & (DIN-1));
    int t = (int)((idx >> 9) & (NT-1));
    int b = (int)(idx >> 18);
    g_Xh[((size_t)(t*NB + b))*DIN + d] = __float2half_rn(x[idx]);
  }
}

extern "C" __global__ void transpose_kernel(const float* in, __half* out, int R, int C) {
  __shared__ float tile[32][33];
  int cx = blockIdx.x*32, ry = blockIdx.y*32;
  #pragma unroll
  for (int j = 0; j < 4; ++j) {
    int r = ry + threadIdx.y + j*8;
    tile[threadIdx.y + j*8][threadIdx.x] = in[(size_t)r*C + cx + threadIdx.x];
  }
  __syncthreads();
  #pragma unroll
  for (int j = 0; j < 4; ++j) {
    int ro = cx + threadIdx.y + j*8;
    out[(size_t)ro*R + ry + threadIdx.x] = __float2half_rn(tile[threadIdx.x][threadIdx.y + j*8]);
  }
}

// ---------------- prepass GEMM: C[M,4096] = A[M,K] @ WT^T + bias ----------------
#define GA_PITCH 144
#define GST (128*GA_PITCH)
#define GSTB (2*GST)
#define GNST 3
#define GSMEM (GNST*GSTB)

extern "C" __global__ void __launch_bounds__(NTHR, 2)
gemm_kernel(const __half* A, const __half* WT, const float* bias, float* C, int K) {
  extern __shared__ char sm[];
  const int tid = threadIdx.x, lane = tid&31, wid = tid>>5;
  const int wm = wid>>2, wn = wid&3;
  const int r = lane>>2, c2 = lane&3;
  const int sub = lane>>3, rsel = lane&7;
  const int bm = blockIdx.x, bn = blockIdx.y;
  const int NC = K >> 6;
  const unsigned sbase = sptr(sm);

  float acc[4][4][4];
  #pragma unroll
  for (int j = 0; j < 4; ++j) {
    float2 bv = *(const float2*)(bias + bn*128 + wn*32 + j*8 + 2*c2);
    #pragma unroll
    for (int mt = 0; mt < 4; ++mt) {
      acc[mt][j][0]=bv.x; acc[mt][j][1]=bv.y; acc[mt][j][2]=bv.x; acc[mt][j][3]=bv.y;
    }
  }

#define GSTG(CH) do {                                                       \
    unsigned base = sbase + ((CH)%3)*GSTB;                                  \
    _Pragma("unroll")                                                       \
    for (int jj = 0; jj < 4; ++jj) {                                        \
      int idx = tid + jj*NTHR, row = idx>>3, seg = idx&7;                   \
      cp16(base + row*GA_PITCH + seg*16,                                    \
           A + (size_t)(bm*128+row)*K + (CH)*64 + seg*8);                   \
      cp16(base + GST + row*GA_PITCH + seg*16,                              \
           WT + (size_t)(bn*128+row)*K + (CH)*64 + seg*8);                  \
    }                                                                       \
    cpcommit();                                                             \
  } while(0)

  GSTG(0); GSTG(1);
  #pragma unroll 1
  for (int ch = 0; ch < NC; ++ch) {
    if (ch+2 < NC) { GSTG(ch+2); cpwait2(); }
    else if (ch+1 < NC) cpwait1();
    else cpwait0();
    __syncthreads();
    unsigned ab = sbase + (ch%3)*GSTB;
    unsigned bb = ab + GST;
    #pragma unroll
    for (int s = 0; s < 4; ++s) {
      unsigned av[4][4];
      #pragma unroll
      for (int mt = 0; mt < 4; ++mt)
        ldsm4(av[mt], ab + (wm*64 + mt*16 + (sub&1)*8 + rsel)*GA_PITCH
                         + s*32 + (sub>>1)*16);
      #pragma unroll
      for (int nt = 0; nt < 2; ++nt) {
        unsigned bv[4];
        ldsm4(bv, bb + (wn*32 + nt*16 + (sub>>1)*8 + rsel)*GA_PITCH
                     + s*32 + (sub&1)*16);
        #pragma unroll
        for (int mt = 0; mt < 4; ++mt) {
          hmma(acc[mt][nt*2],   av[mt], bv);
          hmma(acc[mt][nt*2+1], av[mt], bv+2);
        }
      }
    }
    __syncthreads();
  }
#undef GSTG

  #pragma unroll
  for (int mt = 0; mt < 4; ++mt) {
    int row = bm*128 + wm*64 + mt*16 + r;
    #pragma unroll
    for (int j = 0; j < 4; ++j) {
      int col = bn*128 + wn*32 + j*8 + 2*c2;
      float* p = C + (size_t)row*4096 + col;
      *(float2*)p            = make_float2(acc[mt][j][0], acc[mt][j][1]);
      *(float2*)(p + 8*4096) = make_float2(acc[mt][j][2], acc[mt][j][3]);
    }
  }
}

// ---------------- recurrent kernel ----------------
#define AWP 528
#define AWB (32*AWP)
#define UPH 1032
#define RPACC_OFF 135168
#define RPACC_PITCH 40
#define RGB_OFF  176128
#define RGB_PITCH 40
#define RCS_OFF  186368          // 512 f32 = 2048
#define RH_OFF   188416          // 64x8 halves = 1024
#define RFO_OFF  189440          // 64x8 f32 = 2048
#define RSMEM    191488

template<int LAYER>
__global__ void __launch_bounds__(NTHR, 1)
rec_kernel(const float* h0, const float* c0, const __half* UT,
           float* out, int out_size)
{
  extern __shared__ char sm[];
  float* pacc = (float*)(sm + RPACC_OFF);
  float* gbs  = (float*)(sm + RGB_OFF);
  float* cs   = (float*)(sm + RCS_OFF);
  __half* hsm = (__half*)(sm + RH_OFF);
  float* fo   = (float*)(sm + RFO_OFF);
  const int tid = threadIdx.x, cta = blockIdx.x;
  const int lane = tid&31, wid = tid>>5;
  const int wm = wid&1, ks = wid>>1;
  const int r = lane>>2, c2 = lane&3;
  const int sub = lane>>3, rsel = lane&7;

  // ---- init c, h0 ----
  #pragma unroll
  for (int e0 = 0; e0 < 2; ++e0) {
    int item = tid + e0*NTHR;
    int b = item>>3, hc = item&7, col = cta*8 + hc;
    cs[item] = c0[b*HID + col];
    g_H[0][b*HID + col] = __float2half_rn(h0[b*HID + col]);
  }

  // ---- U bounce -> register fragments ----
  {
    __half* ub = (__half*)sm;
    unsigned du = sptr(ub);
    #pragma unroll
    for (int j = 0; j < 16; ++j) {
      int idx = tid + j*NTHR;
      int row = idx >> 7, seg = idx & 127;
      int gcol = (row>>3)*HID + cta*8 + (row&7);
      cp16(du + row*(UPH*2) + seg*16, UT + (size_t)gcol*HID + seg*8);
    }
    cpcommit(); cpwait0();
  }
  __syncthreads();

  unsigned bfr[16][4][2];
  {
    const __half* ub = (const __half*)sm;
    #pragma unroll
    for (int s = 0; s < 16; ++s) {
      int k = ks*256 + s*16 + 2*c2;
      #pragma unroll
      for (int nt = 0; nt < 4; ++nt) {
        const __half* p = ub + (nt*8 + r)*UPH + k;
        bfr[s][nt][0] = *(const unsigned*)(p);
        bfr[s][nt][1] = *(const unsigned*)(p + 8);
      }
    }
  }
  __syncthreads();
  gridbar();

  unsigned wbs = sptr(sm) + wid*AWB;
  unsigned gbd = sptr(sm + RGB_OFF);

  for (int t = 0; t < NT; ++t) {
    const __half* hs = g_H[t&1];

    // groups: A k-half0 (g1), A k-half1 (g2), gate-base (g3, drains during MMA)
    {
      int rofs = lane>>4, seg = lane&15;
      #pragma unroll
      for (int i = 0; i < 16; ++i) {
        int row = 2*i + rofs;
        cp16(wbs + row*AWP + seg*16,
             hs + (size_t)(wm*32 + row)*HID + ks*256 + seg*8);
      }
      cpcommit();
      #pragma unroll
      for (int i = 0; i < 16; ++i) {
        int row = 2*i + rofs;
        cp16(wbs + row*AWP + 256 + seg*16,
             hs + (size_t)(wm*32 + row)*HID + ks*256 + 128 + seg*8);
      }
      cpcommit();
    }
    #pragma unroll
    for (int j = 0; j < 2; ++j) {
      int idx = tid + j*NTHR;
      int b = idx>>3, q = idx&7;
      cp16(gbd + (b*RGB_PITCH + (q>>1)*8 + (q&1)*4)*4,
           g_GB + ((size_t)(t*NB + b))*4096 + (q>>1)*1024 + cta*8 + (q&1)*4);
    }
    cpcommit();

    float acc[2][4][4];
    #pragma unroll
    for (int mt = 0; mt < 2; ++mt)
      #pragma unroll
      for (int nt = 0; nt < 4; ++nt)
        acc[mt][nt][0]=acc[mt][nt][1]=acc[mt][nt][2]=acc[mt][nt][3]=0.f;

    cpwait2(); __syncwarp();        // A half 0 landed
    #pragma unroll
    for (int s = 0; s < 8; ++s) {
      unsigned av[2][4];
      #pragma unroll
      for (int mt = 0; mt < 2; ++mt)
        ldsm4(av[mt], wbs + (mt*16 + (sub&1)*8 + rsel)*AWP + s*32 + (sub>>1)*16);
      #pragma unroll
      for (int nt = 0; nt < 4; ++nt)
        #pragma unroll
        for (int mt = 0; mt < 2; ++mt)
          hmma(acc[mt][nt], av[mt], bfr[s][nt]);
    }
    cpwait1(); __syncwarp();        // A half 1 landed
    #pragma unroll
    for (int s = 8; s < 16; ++s) {
      unsigned av[2][4];
      #pragma unroll
      for (int mt = 0; mt < 2; ++mt)
        ldsm4(av[mt], wbs + (mt*16 + (sub&1)*8 + rsel)*AWP + s*32 + (sub>>1)*16);
      #pragma unroll
      for (int nt = 0; nt < 4; ++nt)
        #pragma unroll
        for (int mt = 0; mt < 2; ++mt)
          hmma(acc[mt][nt], av[mt], bfr[s][nt]);
    }

    // k-split partials
    #pragma unroll
    for (int mt = 0; mt < 2; ++mt) {
      int row = wm*32 + mt*16 + r;
      #pragma unroll
      for (int nt = 0; nt < 4; ++nt) {
        int col = nt*8 + 2*c2;
        float* p = pacc + (ks*64 + row)*RPACC_PITCH + col;
        *(float2*)p                   = make_float2(acc[mt][nt][0], acc[mt][nt][1]);
        *(float2*)(p + 8*RPACC_PITCH) = make_float2(acc[mt][nt][2], acc[mt][nt][3]);
      }
    }
    cpwait0();                      // gate-base landed (during MMA)
    __syncthreads();

    // reduce + gate base + cell update -> smem staging
    #pragma unroll
    for (int e0 = 0; e0 < 2; ++e0) {
      int item = tid + e0*NTHR;
      int b = item>>3, hc = item&7;
      const float* gb = gbs + b*RGB_PITCH;
      float gi=gb[hc], gf=gb[8+hc], gg=gb[16+hc], go=gb[24+hc];
      #pragma unroll
      for (int q = 0; q < 4; ++q) {
        const float* p = pacc + (q*64 + b)*RPACC_PITCH;
        gi += p[hc]; gf += p[8+hc]; gg += p[16+hc]; go += p[24+hc];
      }
      float cprev = cs[item];
      float cn = sigf(gf)*cprev + sigf(gi)*tanhfast(gg);
      float hn = sigf(go)*tanhfast(cn);
      cs[item] = cn;
      hsm[item] = __float2half_rn(hn);
      if (LAYER == 1) {
        fo[item] = hn;
        if (t == NT-1 && out_size >= NB*NT*HID + 2*NB*HID) {
          int col = cta*8 + hc;
          out[(size_t)NB*NT*HID + b*HID + col]          = hn;
          out[(size_t)NB*NT*HID + NB*HID + b*HID + col] = cn;
        }
      }
    }
    __syncthreads();

    // vectorized global stores
    if (tid < 64) {
      *(uint4*)&g_H[(t+1)&1][(size_t)tid*HID + cta*8] = *(const uint4*)(hsm + tid*8);
    } else if (LAYER == 0) {
      if (tid < 128) {
        int b = tid - 64;
        *(uint4*)&g_X1[((size_t)(t*NB + b))*HID + cta*8] = *(const uint4*)(hsm + b*8);
      }
    } else {
      if (tid < 192) {
        int i = tid - 64, b = i>>1, hf = i&1;
        *(uint4*)&out[((size_t)b*NT + t)*HID + cta*8 + hf*4] = *(const uint4*)(fo + b*8 + hf*4);
      }
    }
    gridbar();
  }
}

// ---------------- host launch ----------------
extern "C" void kernel_launch(void* const* d_in, const int* in_sizes, int n_in,
                              void* d_out, int out_size) {
  const float* x  = (const float*)d_in[0];
  const float* h0 = (const float*)d_in[1];
  const float* c0 = (const float*)d_in[2];
  const float* W0 = (const float*)d_in[3];
  const float* U0 = (const float*)d_in[4];
  const float* b0 = (const float*)d_in[5];
  const float* W1 = (const float*)d_in[6];
  const float* U1 = (const float*)d_in[7];
  const float* b1 = (const float*)d_in[8];
  float* out = (float*)d_out;

  cudaFuncSetAttribute(gemm_kernel, cudaFuncAttributeMaxDynamicSharedMemorySize, GSMEM);
  cudaFuncSetAttribute(rec_kernel<0>, cudaFuncAttributeMaxDynamicSharedMemorySize, RSMEM);
  cudaFuncSetAttribute(rec_kernel<1>, cudaFuncAttributeMaxDynamicSharedMemorySize, RSMEM);

  __half *pW0T, *pW1T, *pU0T, *pU1T, *pXh, *pX1;
  float* pGB;
  cudaGetSymbolAddress((void**)&pW0T, g_W0T);
  cudaGetSymbolAddress((void**)&pW1T, g_W1T);
  cudaGetSymbolAddress((void**)&pU0T, g_U0T);
  cudaGetSymbolAddress((void**)&pU1T, g_U1T);
  cudaGetSymbolAddress((void**)&pXh,  g_Xh);
  cudaGetSymbolAddress((void**)&pX1,  g_X1);
  cudaGetSymbolAddress((void**)&pGB,  g_GB);

  dim3 tb(32, 8);
  // order chosen so rec_kernel<0> is the 5th launch (ncu capture slot)
  conv_x_kernel<<<512, 256>>>(x);                                            // 1
  transpose_kernel<<<dim3(4*HID/32, HID/32), tb>>>(U0, pU0T, HID, 4*HID);    // 2
  transpose_kernel<<<dim3(4*HID/32, DIN/32), tb>>>(W0, pW0T, DIN, 4*HID);    // 3
  gemm_kernel<<<dim3(NT*NB/128, 4*HID/128), NTHR, GSMEM>>>(pXh, pW0T, b0, pGB, DIN); // 4
  rec_kernel<0><<<NCTA, NTHR, RSMEM>>>(h0, c0, pU0T, out, out_size);         // 5
  transpose_kernel<<<dim3(4*HID/32, HID/32), tb>>>(W1, pW1T, HID, 4*HID);    // 6
  transpose_kernel<<<dim3(4*HID/32, HID/32), tb>>>(U1, pU1T, HID, 4*HID);    // 7
  gemm_kernel<<<dim3(NT*NB/128, 4*HID/128), NTHR, GSMEM>>>(pX1, pW1T, b1, pGB, HID); // 8
  rec_kernel<1><<<NCTA, NTHR, RSMEM>>>(h0 + NB*HID, c0 + NB*HID, pU1T, out, out_size); // 9
}

// round 8
// speedup vs baseline: 1.5964x; 1.1544x over previous
#include <cuda_runtime.h>
#include <cuda_fp16.h>

#define NB 64
#define NT 512
#define DIN 512
#define HID 1024
#define NCTA 128
#define NTHR 256
#define CLSZ 4

// ---------------- global scratch ----------------
__device__ __align__(256) __half g_Xh[NT*NB*DIN];
__device__ __align__(256) __half g_X1[NT*NB*HID];
__device__ __align__(256) float  g_GB[(size_t)NT*NB*4*HID];
__device__ __align__(256) __half g_W0T[4*HID*DIN];
__device__ __align__(256) __half g_W1T[4*HID*HID];
__device__ __align__(256) __half g_U0T[4*HID*HID];
__device__ __align__(256) __half g_U1T[4*HID*HID];
__device__ __align__(256) __half g_H[2][NB*HID];
__device__ unsigned g_bar;

// ---------------- helpers ----------------
__device__ __forceinline__ unsigned sptr(const void* p) {
  return (unsigned)__cvta_generic_to_shared(p);
}
__device__ __forceinline__ void cp16(unsigned d, const void* s) {
  asm volatile("cp.async.cg.shared.global [%0], [%1], 16;" :: "r"(d), "l"(s));
}
__device__ __forceinline__ void cpcommit() { asm volatile("cp.async.commit_group;"); }
__device__ __forceinline__ void cpwait0()  { asm volatile("cp.async.wait_group 0;"); }
__device__ __forceinline__ void cpwait1()  { asm volatile("cp.async.wait_group 1;"); }
__device__ __forceinline__ void cpwait2()  { asm volatile("cp.async.wait_group 2;"); }

__device__ __forceinline__ void ldsm4(unsigned* r, unsigned addr) {
  asm volatile("ldmatrix.sync.aligned.m8n8.x4.shared.b16 {%0,%1,%2,%3}, [%4];"
    : "=r"(r[0]), "=r"(r[1]), "=r"(r[2]), "=r"(r[3]) : "r"(addr));
}
__device__ __forceinline__ void hmma(float* d, const unsigned* a, const unsigned* b) {
  asm volatile("mma.sync.aligned.m16n8k16.row.col.f32.f16.f16.f32 "
    "{%0,%1,%2,%3}, {%4,%5,%6,%7}, {%8,%9}, {%0,%1,%2,%3};"
    : "+f"(d[0]), "+f"(d[1]), "+f"(d[2]), "+f"(d[3])
    : "r"(a[0]), "r"(a[1]), "r"(a[2]), "r"(a[3]), "r"(b[0]), "r"(b[1]));
}
__device__ __forceinline__ void gridbar() {
  __syncthreads();
  if (threadIdx.x == 0) {
    unsigned t, cur;
    asm volatile("atom.add.release.gpu.u32 %0, [%1], 1;" : "=r"(t) : "l"(&g_bar) : "memory");
    unsigned target = (t & ~(unsigned)(NCTA-1)) + NCTA;
    do {
      asm volatile("ld.acquire.gpu.u32 %0, [%1];" : "=r"(cur) : "l"(&g_bar) : "memory");
    } while ((int)(cur - target) < 0);
  }
  __syncthreads();
}
__device__ __forceinline__ float sigf(float x)     { return 1.f/(1.f+__expf(-x)); }
__device__ __forceinline__ float tanhfast(float x) { return 1.f - 2.f/(1.f+__expf(2.f*x)); }

// mbarrier + bulk multicast
__device__ __forceinline__ void mbar_init(unsigned mbar, unsigned cnt) {
  asm volatile("mbarrier.init.shared.b64 [%0], %1;" :: "r"(mbar), "r"(cnt) : "memory");
}
__device__ __forceinline__ void mbar_expect(unsigned mbar, unsigned bytes) {
  asm volatile("mbarrier.arrive.expect_tx.shared.b64 _, [%0], %1;"
    :: "r"(mbar), "r"(bytes) : "memory");
}
__device__ __forceinline__ void mbar_wait(unsigned mbar, unsigned parity) {
  asm volatile(
    "{\n\t.reg .pred p;\n\t"
    "WAIT_%=:\n\t"
    "mbarrier.try_wait.parity.acquire.cta.shared::cta.b64 p, [%0], %1, 0x989680;\n\t"
    "@!p bra WAIT_%=;\n\t}"
    :: "r"(mbar), "r"(parity) : "memory");
}
__device__ __forceinline__ void bulk_mc(unsigned dst, const void* src, unsigned bytes,
                                        unsigned mbar, unsigned short mask) {
  asm volatile(
    "cp.async.bulk.shared::cluster.global.mbarrier::complete_tx::bytes.multicast::cluster "
    "[%0], [%1], %2, [%3], %4;"
    :: "r"(dst), "l"(src), "r"(bytes), "r"(mbar), "h"(mask) : "memory");
}
__device__ __forceinline__ unsigned ctarank() {
  unsigned r; asm("mov.u32 %0, %%cluster_ctarank;" : "=r"(r)); return r;
}

// ---------------- prep kernels ----------------
extern "C" __global__ void conv_x_kernel(const float* x) {
  for (size_t idx = (size_t)blockIdx.x*blockDim.x + threadIdx.x;
       idx < (size_t)NB*NT*DIN; idx += (size_t)gridDim.x*blockDim.x) {
    int d = (int)(idx & (DIN-1));
    int t = (int)((idx >> 9) & (NT-1));
    int b = (int)(idx >> 18);
    g_Xh[((size_t)(t*NB + b))*DIN + d] = __float2half_rn(x[idx]);
  }
}

extern "C" __global__ void transpose_kernel(const float* in, __half* out, int R, int C) {
  __shared__ float tile[32][33];
  int cx = blockIdx.x*32, ry = blockIdx.y*32;
  #pragma unroll
  for (int j = 0; j < 4; ++j) {
    int r = ry + threadIdx.y + j*8;
    tile[threadIdx.y + j*8][threadIdx.x] = in[(size_t)r*C + cx + threadIdx.x];
  }
  __syncthreads();
  #pragma unroll
  for (int j = 0; j < 4; ++j) {
    int ro = cx + threadIdx.y + j*8;
    out[(size_t)ro*R + ry + threadIdx.x] = __float2half_rn(tile[threadIdx.x][threadIdx.y + j*8]);
  }
}

// ---------------- prepass GEMM: C[M,4096] = A[M,K] @ WT^T + bias ----------------
#define GA_PITCH 144
#define GST (128*GA_PITCH)
#define GSTB (2*GST)
#define GNST 3
#define GSMEM (GNST*GSTB)

extern "C" __global__ void __launch_bounds__(NTHR, 2)
gemm_kernel(const __half* A, const __half* WT, const float* bias, float* C, int K) {
  extern __shared__ char sm[];
  const int tid = threadIdx.x, lane = tid&31, wid = tid>>5;
  const int wm = wid>>2, wn = wid&3;
  const int r = lane>>2, c2 = lane&3;
  const int sub = lane>>3, rsel = lane&7;
  const int bm = blockIdx.x, bn = blockIdx.y;
  const int NC = K >> 6;
  const unsigned sbase = sptr(sm);

  float acc[4][4][4];
  #pragma unroll
  for (int j = 0; j < 4; ++j) {
    float2 bv = *(const float2*)(bias + bn*128 + wn*32 + j*8 + 2*c2);
    #pragma unroll
    for (int mt = 0; mt < 4; ++mt) {
      acc[mt][j][0]=bv.x; acc[mt][j][1]=bv.y; acc[mt][j][2]=bv.x; acc[mt][j][3]=bv.y;
    }
  }

#define GSTG(CH) do {                                                       \
    unsigned base = sbase + ((CH)%3)*GSTB;                                  \
    _Pragma("unroll")                                                       \
    for (int jj = 0; jj < 4; ++jj) {                                        \
      int idx = tid + jj*NTHR, row = idx>>3, seg = idx&7;                   \
      cp16(base + row*GA_PITCH + seg*16,                                    \
           A + (size_t)(bm*128+row)*K + (CH)*64 + seg*8);                   \
      cp16(base + GST + row*GA_PITCH + seg*16,                              \
           WT + (size_t)(bn*128+row)*K + (CH)*64 + seg*8);                  \
    }                                                                       \
    cpcommit();                                                             \
  } while(0)

  GSTG(0); GSTG(1);
  #pragma unroll 1
  for (int ch = 0; ch < NC; ++ch) {
    if (ch+2 < NC) { GSTG(ch+2); cpwait2(); }
    else if (ch+1 < NC) cpwait1();
    else cpwait0();
    __syncthreads();
    unsigned ab = sbase + (ch%3)*GSTB;
    unsigned bb = ab + GST;
    #pragma unroll
    for (int s = 0; s < 4; ++s) {
      unsigned av[4][4];
      #pragma unroll
      for (int mt = 0; mt < 4; ++mt)
        ldsm4(av[mt], ab + (wm*64 + mt*16 + (sub&1)*8 + rsel)*GA_PITCH
                         + s*32 + (sub>>1)*16);
      #pragma unroll
      for (int nt = 0; nt < 2; ++nt) {
        unsigned bv[4];
        ldsm4(bv, bb + (wn*32 + nt*16 + (sub>>1)*8 + rsel)*GA_PITCH
                     + s*32 + (sub&1)*16);
        #pragma unroll
        for (int mt = 0; mt < 4; ++mt) {
          hmma(acc[mt][nt*2],   av[mt], bv);
          hmma(acc[mt][nt*2+1], av[mt], bv+2);
        }
      }
    }
    __syncthreads();
  }
#undef GSTG

  #pragma unroll
  for (int mt = 0; mt < 4; ++mt) {
    int row = bm*128 + wm*64 + mt*16 + r;
    #pragma unroll
    for (int j = 0; j < 4; ++j) {
      int col = bn*128 + wn*32 + j*8 + 2*c2;
      float* p = C + (size_t)row*4096 + col;
      *(float2*)p            = make_float2(acc[mt][j][0], acc[mt][j][1]);
      *(float2*)(p + 8*4096) = make_float2(acc[mt][j][2], acc[mt][j][3]);
    }
  }
}

// ---------------- recurrent kernel ----------------
// A buffer: 64 rows x 2064 B (2048 data + 16 pad) = 132096; ldmatrix conflict-free.
#define ARP 2064
#define UPH 1032
#define RPACC_OFF 132096
#define RPACC_PITCH 40
#define RGB_OFF  173056
#define RGB_PITCH 40
#define RCS_OFF  183296
#define RH_OFF   185344
#define RFO_OFF  186368
#define RMB_OFF  188416        // 4 mbarriers (8B each)
#define RSMEM    188544

template<int LAYER>
__global__ void __launch_bounds__(NTHR, 1) __cluster_dims__(CLSZ, 1, 1)
rec_kernel(const float* h0, const float* c0, const __half* UT,
           float* out, int out_size)
{
  extern __shared__ char sm[];
  float* pacc = (float*)(sm + RPACC_OFF);
  float* gbs  = (float*)(sm + RGB_OFF);
  float* cs   = (float*)(sm + RCS_OFF);
  __half* hsm = (__half*)(sm + RH_OFF);
  float* fo   = (float*)(sm + RFO_OFF);
  const int tid = threadIdx.x, cta = blockIdx.x;
  const int lane = tid&31, wid = tid>>5;
  const int wm = wid&1, ks = wid>>1;
  const int r = lane>>2, c2 = lane&3;
  const int sub = lane>>3, rsel = lane&7;
  const unsigned rank = ctarank();
  const unsigned abase = sptr(sm);
  const unsigned mb = sptr(sm + RMB_OFF);   // [half][t&1]: mb + (half*2 + (t&1))*8

  // ---- init c, h0 ----
  #pragma unroll
  for (int e0 = 0; e0 < 2; ++e0) {
    int item = tid + e0*NTHR;
    int b = item>>3, hc = item&7, col = cta*8 + hc;
    cs[item] = c0[b*HID + col];
    g_H[0][b*HID + col] = __float2half_rn(h0[b*HID + col]);
  }

  // ---- U bounce -> register fragments (uses A-buffer region, drained before use) ----
  {
    __half* ub = (__half*)sm;
    unsigned du = sptr(ub);
    #pragma unroll
    for (int j = 0; j < 16; ++j) {
      int idx = tid + j*NTHR;
      int row = idx >> 7, seg = idx & 127;
      int gcol = (row>>3)*HID + cta*8 + (row&7);
      cp16(du + row*(UPH*2) + seg*16, UT + (size_t)gcol*HID + seg*8);
    }
    cpcommit(); cpwait0();
  }
  __syncthreads();

  unsigned bfr[16][4][2];
  {
    const __half* ub = (const __half*)sm;
    #pragma unroll
    for (int s = 0; s < 16; ++s) {
      int k = ks*256 + s*16 + 2*c2;
      #pragma unroll
      for (int nt = 0; nt < 4; ++nt) {
        const __half* p = ub + (nt*8 + r)*UPH + k;
        bfr[s][nt][0] = *(const unsigned*)(p);
        bfr[s][nt][1] = *(const unsigned*)(p + 8);
      }
    }
  }
  __syncthreads();

  if (tid == 0) {
    #pragma unroll
    for (int i = 0; i < 4; ++i) mbar_init(mb + i*8, 1);
  }
  __syncthreads();
  asm volatile("barrier.cluster.arrive.aligned;" ::: "memory");
  asm volatile("barrier.cluster.wait.aligned;" ::: "memory");
  gridbar();

  unsigned gbd = sptr(sm + RGB_OFF);

  for (int t = 0; t < NT; ++t) {
    const __half* hs = g_H[t&1];
    const unsigned par = (t>>1)&1;

    // issue h multicast: this CTA owns rows [16*rank, +16)
    if (tid == 0) {
      unsigned mbA = mb + (0*2 + (t&1))*8;
      unsigned mbB = mb + (1*2 + (t&1))*8;
      mbar_expect(mbA, 32*2048);
      mbar_expect(mbB, 32*2048);
      unsigned mymb = (rank < 2) ? mbA : mbB;
      int row0 = rank*16;
      #pragma unroll
      for (int i = 0; i < 16; ++i) {
        int row = row0 + i;
        bulk_mc(abase + row*ARP, hs + (size_t)row*HID, 2048, mymb, (unsigned short)0xF);
      }
    }

    // gate-base prefetch (drains under MMA)
    #pragma unroll
    for (int j = 0; j < 2; ++j) {
      int idx = tid + j*NTHR;
      int b = idx>>3, q = idx&7;
      cp16(gbd + (b*RGB_PITCH + (q>>1)*8 + (q&1)*4)*4,
           g_GB + ((size_t)(t*NB + b))*4096 + (q>>1)*1024 + cta*8 + (q&1)*4);
    }
    cpcommit();

    float acc[2][4][4];
    #pragma unroll
    for (int mt = 0; mt < 2; ++mt)
      #pragma unroll
      for (int nt = 0; nt < 4; ++nt)
        acc[mt][nt][0]=acc[mt][nt][1]=acc[mt][nt][2]=acc[mt][nt][3]=0.f;

    // wait for this m-half's rows, then MMA
    mbar_wait(mb + (wm*2 + (t&1))*8, par);
    #pragma unroll
    for (int s = 0; s < 16; ++s) {
      unsigned av[2][4];
      #pragma unroll
      for (int mt = 0; mt < 2; ++mt) {
        int row = wm*32 + mt*16 + (sub&1)*8 + rsel;
        ldsm4(av[mt], abase + row*ARP + ks*512 + s*32 + (sub>>1)*16);
      }
      #pragma unroll
      for (int nt = 0; nt < 4; ++nt)
        #pragma unroll
        for (int mt = 0; mt < 2; ++mt)
          hmma(acc[mt][nt], av[mt], bfr[s][nt]);
    }

    // k-split partials
    #pragma unroll
    for (int mt = 0; mt < 2; ++mt) {
      int row = wm*32 + mt*16 + r;
      #pragma unroll
      for (int nt = 0; nt < 4; ++nt) {
        int col = nt*8 + 2*c2;
        float* p = pacc + (ks*64 + row)*RPACC_PITCH + col;
        *(float2*)p                   = make_float2(acc[mt][nt][0], acc[mt][nt][1]);
        *(float2*)(p + 8*RPACC_PITCH) = make_float2(acc[mt][nt][2], acc[mt][nt][3]);
      }
    }
    cpwait0();                      // gate-base landed
    __syncthreads();

    // reduce + gate base + cell update -> smem staging
    #pragma unroll
    for (int e0 = 0; e0 < 2; ++e0) {
      int item = tid + e0*NTHR;
      int b = item>>3, hc = item&7;
      const float* gb = gbs + b*RGB_PITCH;
      float gi=gb[hc], gf=gb[8+hc], gg=gb[16+hc], go=gb[24+hc];
      #pragma unroll
      for (int q = 0; q < 4; ++q) {
        const float* p = pacc + (q*64 + b)*RPACC_PITCH;
        gi += p[hc]; gf += p[8+hc]; gg += p[16+hc]; go += p[24+hc];
      }
      float cprev = cs[item];
      float cn = sigf(gf)*cprev + sigf(gi)*tanhfast(gg);
      float hn = sigf(go)*tanhfast(cn);
      cs[item] = cn;
      hsm[item] = __float2half_rn(hn);
      if (LAYER == 1) {
        fo[item] = hn;
        if (t == NT-1 && out_size >= NB*NT*HID + 2*NB*HID) {
          int col = cta*8 + hc;
          out[(size_t)NB*NT*HID + b*HID + col]          = hn;
          out[(size_t)NB*NT*HID + NB*HID + b*HID + col] = cn;
        }
      }
    }
    __syncthreads();

    // vectorized global stores
    if (tid < 64) {
      *(uint4*)&g_H[(t+1)&1][(size_t)tid*HID + cta*8] = *(const uint4*)(hsm + tid*8);
    } else if (LAYER == 0) {
      if (tid < 128) {
        int b = tid - 64;
        *(uint4*)&g_X1[((size_t)(t*NB + b))*HID + cta*8] = *(const uint4*)(hsm + b*8);
      }
    } else {
      if (tid < 192) {
        int i = tid - 64, b = i>>1, hf = i&1;
        *(uint4*)&out[((size_t)b*NT + t)*HID + cta*8 + hf*4] = *(const uint4*)(fo + b*8 + hf*4);
      }
    }
    gridbar();
  }
}

// ---------------- host launch ----------------
extern "C" void kernel_launch(void* const* d_in, const int* in_sizes, int n_in,
                              void* d_out, int out_size) {
  const float* x  = (const float*)d_in[0];
  const float* h0 = (const float*)d_in[1];
  const float* c0 = (const float*)d_in[2];
  const float* W0 = (const float*)d_in[3];
  const float* U0 = (const float*)d_in[4];
  const float* b0 = (const float*)d_in[5];
  const float* W1 = (const float*)d_in[6];
  const float* U1 = (const float*)d_in[7];
  const float* b1 = (const float*)d_in[8];
  float* out = (float*)d_out;

  cudaFuncSetAttribute(gemm_kernel, cudaFuncAttributeMaxDynamicSharedMemorySize, GSMEM);
  cudaFuncSetAttribute(rec_kernel<0>, cudaFuncAttributeMaxDynamicSharedMemorySize, RSMEM);
  cudaFuncSetAttribute(rec_kernel<1>, cudaFuncAttributeMaxDynamicSharedMemorySize, RSMEM);

  __half *pW0T, *pW1T, *pU0T, *pU1T, *pXh, *pX1;
  float* pGB;
  cudaGetSymbolAddress((void**)&pW0T, g_W0T);
  cudaGetSymbolAddress((void**)&pW1T, g_W1T);
  cudaGetSymbolAddress((void**)&pU0T, g_U0T);
  cudaGetSymbolAddress((void**)&pU1T, g_U1T);
  cudaGetSymbolAddress((void**)&pXh,  g_Xh);
  cudaGetSymbolAddress((void**)&pX1,  g_X1);
  cudaGetSymbolAddress((void**)&pGB,  g_GB);

  dim3 tb(32, 8);
  // order chosen so rec_kernel<0> is the 5th launch (ncu capture slot)
  conv_x_kernel<<<512, 256>>>(x);                                            // 1
  transpose_kernel<<<dim3(4*HID/32, HID/32), tb>>>(U0, pU0T, HID, 4*HID);    // 2
  transpose_kernel<<<dim3(4*HID/32, DIN/32), tb>>>(W0, pW0T, DIN, 4*HID);    // 3
  gemm_kernel<<<dim3(NT*NB/128, 4*HID/128), NTHR, GSMEM>>>(pXh, pW0T, b0, pGB, DIN); // 4
  rec_kernel<0><<<NCTA, NTHR, RSMEM>>>(h0, c0, pU0T, out, out_size);         // 5
  transpose_kernel<<<dim3(4*HID/32, HID/32), tb>>>(W1, pW1T, HID, 4*HID);    // 6
  transpose_kernel<<<dim3(4*HID/32, HID/32), tb>>>(U1, pU1T, HID, 4*HID);    // 7
  gemm_kernel<<<dim3(NT*NB/128, 4*HID/128), NTHR, GSMEM>>>(pX1, pW1T, b1, pGB, HID); // 8
  rec_kernel<1><<<NCTA, NTHR, RSMEM>>>(h0 + NB*HID, c0 + NB*HID, pU1T, out, out_size); // 9
}